// round 4
// baseline (speedup 1.0000x reference)
#include <cuda_runtime.h>

// FlowComposite: flows [B,T,2,H,W] fp32 -> out [B,2,H,W] fp32.
// R4: R3's float4 gather (4 LDG.128/px/step instead of 8 scalar LDG, halving
// L1tex wavefronts) with the left-edge fix: the x0+1 corner's clamped column
// xc1 is computed independently and selected via o1 = xc1 - a in {0..4}
// (4 = straddle -> predicated scalar fixup load). Loads/sums bit-match R2.

static constexpr int Bc = 8;
static constexpr int Tc = 12;
static constexpr int Hc = 544;
static constexpr int Wc = 960;
static constexpr int HW = Hc * Wc;

__device__ __forceinline__ float pick4(const float4& q, int o) {
    // o in {0,1,2,3}
    return (o & 2) ? ((o & 1) ? q.w : q.z) : ((o & 1) ? q.y : q.x);
}

__device__ __forceinline__ float pick5(const float4& q, float e, int o) {
    // o in {0,1,2,3,4}; 4 selects the fixup element e
    return (o >= 4) ? e : pick4(q, o);
}

__global__ __launch_bounds__(256)
void flow_composite_kernel(const float* __restrict__ flows, float* __restrict__ out) {
    // 64x4 pixel tile per block (keeps vertical gather reuse in one L1)
    const int x = (blockIdx.x << 6) + (threadIdx.x & 63);
    const int y = (blockIdx.y << 2) + (threadIdx.x >> 6);
    const int b = blockIdx.z;

    const float xf = (float)x;
    const float yf = (float)y;

    float u = 0.0f, v = 0.0f;
    const float* fb = flows + (unsigned)b * (Tc * 2 * HW);

    #pragma unroll
    for (int t = 0; t < Tc; ++t) {
        const float* f0 = fb + (unsigned)t * (2 * HW);   // u plane
        const float* f1 = f0 + HW;                       // v plane

        const float px = xf + u - 0.5f;
        const float py = yf + v - 0.5f;

        const int x0 = __float2int_rd(px);
        const int y0 = __float2int_rd(py);

        const float wx1 = px - (float)x0;
        const float wy1 = py - (float)y0;
        const float wx0 = 1.0f - wx1;
        const float wy0 = 1.0f - wy1;

        const bool vx0 = (x0 >= 0) && (x0 <= Wc - 1);
        const bool vx1 = (x0 >= -1) && (x0 <= Wc - 2);
        const bool vy0 = (y0 >= 0) && (y0 <= Hc - 1);
        const bool vy1 = (y0 >= -1) && (y0 <= Hc - 2);

        const int xc0 = min(max(x0, 0), Wc - 1);
        const int xc1 = min(max(x0 + 1, 0), Wc - 1);
        const int yc0 = min(max(y0, 0), Hc - 1);
        const int yc1 = min(max(y0 + 1, 0), Hc - 1);

        const float w00 = wx0 * wy0 * ((vx0 && vy0) ? 1.0f : 0.0f);
        const float w10 = wx1 * wy0 * ((vx1 && vy0) ? 1.0f : 0.0f);
        const float w01 = wx0 * wy1 * ((vx0 && vy1) ? 1.0f : 0.0f);
        const float w11 = wx1 * wy1 * ((vx1 && vy1) ? 1.0f : 0.0f);

        // Aligned 16B window containing xc0; xc1 is at a..a+4.
        const int a  = xc0 & ~3;          // 0..956, 16B-aligned column
        const int o0 = xc0 - a;           // 0..3
        const int o1 = xc1 - a;           // 0..4 (0 possible at left edge; 4 = straddle)
        const int i0 = yc0 * Wc + a;
        const int i1 = yc1 * Wc + a;

        // 4 independent LDG.128 gathers (one per row x channel)
        const float4 qu0 = __ldg((const float4*)(f0 + i0));
        const float4 qu1 = __ldg((const float4*)(f0 + i1));
        const float4 qv0 = __ldg((const float4*)(f1 + i0));
        const float4 qv1 = __ldg((const float4*)(f1 + i1));

        // Straddle fixup (o1 == 4): one extra scalar per row x channel.
        float eu0 = 0.0f, eu1 = 0.0f, ev0 = 0.0f, ev1 = 0.0f;
        if (o1 == 4) {
            eu0 = __ldg(f0 + i0 + 4);
            eu1 = __ldg(f0 + i1 + 4);
            ev0 = __ldg(f1 + i0 + 4);
            ev1 = __ldg(f1 + i1 + 4);
        }

        const float a00 = pick4(qu0, o0);
        const float a10 = pick5(qu0, eu0, o1);
        const float a01 = pick4(qu1, o0);
        const float a11 = pick5(qu1, eu1, o1);
        const float c00 = pick4(qv0, o0);
        const float c10 = pick5(qv0, ev0, o1);
        const float c01 = pick4(qv1, o0);
        const float c11 = pick5(qv1, ev1, o1);

        // Same summation order as reference: ((c00 + c10) + c01) + c11
        const float s0 = ((w00 * a00 + w10 * a10) + w01 * a01) + w11 * a11;
        const float s1 = ((w00 * c00 + w10 * c10) + w01 * c01) + w11 * c11;

        u += s0;
        v += s1;
    }

    const int p = y * Wc + x;
    float* ob = out + (unsigned)b * (2 * HW);
    ob[p]      = u;
    ob[HW + p] = v;
}

extern "C" void kernel_launch(void* const* d_in, const int* in_sizes, int n_in,
                              void* d_out, int out_size) {
    const float* flows = (const float*)d_in[0];
    float* out = (float*)d_out;

    dim3 grid(Wc / 64, Hc / 4, Bc);   // exact cover, no tails
    dim3 block(256);
    flow_composite_kernel<<<grid, block>>>(flows, out);
}

// round 5
// speedup vs baseline: 1.4631x; 1.4631x over previous
#include <cuda_runtime.h>

// FlowComposite: flows [B,T,2,H,W] fp32 -> out [B,2,H,W] fp32.
// R5: merge each (x0, x0+1) corner pair into ONE aligned LDG.64 (float2) per
// (row, channel): per-lane window = exactly the 8 needed bytes (unlike R4's
// LDG.128 which paid a 4-wavefront return floor for 2x unneeded data).
// Window base e = xc0 & ~1 is always a valid aligned column (W even).
// Straddle (xc0 odd && xc1 == xc0+1 -> o1 == 2) fixed by predicated scalar
// load at e+2 == xc1. Values/weights/sum order bit-match R2 (rel_err 0.0).

static constexpr int Bc = 8;
static constexpr int Tc = 12;
static constexpr int Hc = 544;
static constexpr int Wc = 960;
static constexpr int HW = Hc * Wc;

__global__ __launch_bounds__(256)
void flow_composite_kernel(const float* __restrict__ flows, float* __restrict__ out) {
    // 64x4 pixel tile per block (keeps vertical gather reuse in one L1)
    const int x = (blockIdx.x << 6) + (threadIdx.x & 63);
    const int y = (blockIdx.y << 2) + (threadIdx.x >> 6);
    const int b = blockIdx.z;

    const float xf = (float)x;
    const float yf = (float)y;

    float u = 0.0f, v = 0.0f;
    const float* fb = flows + (unsigned)b * (Tc * 2 * HW);

    #pragma unroll
    for (int t = 0; t < Tc; ++t) {
        const float* f0 = fb + (unsigned)t * (2 * HW);   // u plane
        const float* f1 = f0 + HW;                       // v plane

        const float px = xf + u - 0.5f;
        const float py = yf + v - 0.5f;

        const int x0 = __float2int_rd(px);
        const int y0 = __float2int_rd(py);

        const float wx1 = px - (float)x0;
        const float wy1 = py - (float)y0;
        const float wx0 = 1.0f - wx1;
        const float wy0 = 1.0f - wy1;

        const bool vx0 = (x0 >= 0) && (x0 <= Wc - 1);
        const bool vx1 = (x0 >= -1) && (x0 <= Wc - 2);
        const bool vy0 = (y0 >= 0) && (y0 <= Hc - 1);
        const bool vy1 = (y0 >= -1) && (y0 <= Hc - 2);

        const int xc0 = min(max(x0, 0), Wc - 1);
        const int xc1 = min(max(x0 + 1, 0), Wc - 1);
        const int yc0 = min(max(y0, 0), Hc - 1);
        const int yc1 = min(max(y0 + 1, 0), Hc - 1);

        const float w00 = wx0 * wy0 * ((vx0 && vy0) ? 1.0f : 0.0f);
        const float w10 = wx1 * wy0 * ((vx1 && vy0) ? 1.0f : 0.0f);
        const float w01 = wx0 * wy1 * ((vx0 && vy1) ? 1.0f : 0.0f);
        const float w11 = wx1 * wy1 * ((vx0 == vx0 && vx1 && vy1) ? 1.0f : 0.0f);

        // Aligned 8B window containing xc0 (and xc0+1 unless xc0 is odd).
        const int e  = xc0 & ~1;          // 0..958; e+1 <= W-1 always valid
        const int o0 = xc0 - e;           // 0 or 1
        const int o1 = xc1 - e;           // 0, 1, or 2 (2 = straddle)
        const int i0 = yc0 * Wc + e;
        const int i1 = yc1 * Wc + e;

        // 4 independent LDG.64 gathers (one per row x channel)
        const float2 qu0 = __ldg((const float2*)(f0 + i0));
        const float2 qu1 = __ldg((const float2*)(f0 + i1));
        const float2 qv0 = __ldg((const float2*)(f1 + i0));
        const float2 qv1 = __ldg((const float2*)(f1 + i1));

        // Straddle fixup: only lanes with o1 == 2 issue these (predicated).
        float eu0 = 0.0f, eu1 = 0.0f, ev0 = 0.0f, ev1 = 0.0f;
        if (o1 == 2) {
            eu0 = __ldg(f0 + i0 + 2);
            eu1 = __ldg(f0 + i1 + 2);
            ev0 = __ldg(f1 + i0 + 2);
            ev1 = __ldg(f1 + i1 + 2);
        }

        // corner at xc0 = q[o0]; corner at xc1 = q[o1] (o1==2 -> fixup)
        const float a00 = o0 ? qu0.y : qu0.x;
        const float a01 = o0 ? qu1.y : qu1.x;
        const float c00 = o0 ? qv0.y : qv0.x;
        const float c01 = o0 ? qv1.y : qv1.x;
        const float a10 = (o1 == 0) ? qu0.x : ((o1 == 1) ? qu0.y : eu0);
        const float a11 = (o1 == 0) ? qu1.x : ((o1 == 1) ? qu1.y : eu1);
        const float c10 = (o1 == 0) ? qv0.x : ((o1 == 1) ? qv0.y : ev0);
        const float c11 = (o1 == 0) ? qv1.x : ((o1 == 1) ? qv1.y : ev1);

        // Same summation order as reference: ((c00 + c10) + c01) + c11
        const float s0 = ((w00 * a00 + w10 * a10) + w01 * a01) + w11 * a11;
        const float s1 = ((w00 * c00 + w10 * c10) + w01 * c01) + w11 * c11;

        u += s0;
        v += s1;
    }

    const int p = y * Wc + x;
    float* ob = out + (unsigned)b * (2 * HW);
    ob[p]      = u;
    ob[HW + p] = v;
}

extern "C" void kernel_launch(void* const* d_in, const int* in_sizes, int n_in,
                              void* d_out, int out_size) {
    const float* flows = (const float*)d_in[0];
    float* out = (float*)d_out;

    dim3 grid(Wc / 64, Hc / 4, Bc);   // exact cover, no tails
    dim3 block(256);
    flow_composite_kernel<<<grid, block>>>(flows, out);
}

// round 6
// speedup vs baseline: 1.8051x; 1.2337x over previous
#include <cuda_runtime.h>

// FlowComposite: flows [B,T,2,H,W] fp32 -> out [B,2,H,W] fp32.
// R6: R2's proven scalar-gather core (8x LDG.32/px/step — measured cheapest
// addressing mode for divergent gathers on sm_103a; .64/.128 merges lose to
// return-bandwidth floors), plus an exact special case for t=0 where u=v=0:
// px = x-0.5 -> all bilinear weights are exactly 0.25*valid and the corner
// loads are fully coherent (x-1,x ; y-1,y). Removes ~1/12 of the divergent
// wavefront bill. Weights & summation order bit-match the reference.

static constexpr int Bc = 8;
static constexpr int Tc = 12;
static constexpr int Hc = 544;
static constexpr int Wc = 960;
static constexpr int HW = Hc * Wc;

__global__ __launch_bounds__(256)
void flow_composite_kernel(const float* __restrict__ flows, float* __restrict__ out) {
    // 64x4 pixel tile per block (keeps vertical gather reuse in one L1)
    const int x = (blockIdx.x << 6) + (threadIdx.x & 63);
    const int y = (blockIdx.y << 2) + (threadIdx.x >> 6);
    const int b = blockIdx.z;

    const float xf = (float)x;
    const float yf = (float)y;

    const float* fb = flows + (unsigned)b * (Tc * 2 * HW);

    // ---- t = 0: u=v=0 exactly -> px = x-0.5, py = y-0.5.
    // x0 = x-1, wx1 = 0.5 exactly; same in y. Weights = 0.25 * validity.
    float u, v;
    {
        const float* f0 = fb;            // u plane, t=0
        const float* f1 = fb + HW;       // v plane, t=0

        const int xm = max(x - 1, 0);
        const int ym = max(y - 1, 0);
        const int r0 = ym * Wc;
        const int r1 = y * Wc;

        const float vx = (x >= 1) ? 1.0f : 0.0f;   // validity of column x-1
        const float vy = (y >= 1) ? 1.0f : 0.0f;   // validity of row y-1
        const float w00 = 0.25f * (vx * vy);
        const float w10 = 0.25f * vy;
        const float w01 = 0.25f * vx;
        const float w11 = 0.25f;

        const float a00 = __ldg(f0 + r0 + xm);
        const float a10 = __ldg(f0 + r0 + x);
        const float a01 = __ldg(f0 + r1 + xm);
        const float a11 = __ldg(f0 + r1 + x);
        const float b00 = __ldg(f1 + r0 + xm);
        const float b10 = __ldg(f1 + r0 + x);
        const float b01 = __ldg(f1 + r1 + xm);
        const float b11 = __ldg(f1 + r1 + x);

        // Same summation order as reference: ((c00 + c10) + c01) + c11
        u = ((w00 * a00 + w10 * a10) + w01 * a01) + w11 * a11;
        v = ((w00 * b00 + w10 * b10) + w01 * b01) + w11 * b11;
    }

    // ---- t = 1..11: generic divergent bilinear gather (R2 form).
    #pragma unroll
    for (int t = 1; t < Tc; ++t) {
        const float* f0 = fb + (unsigned)t * (2 * HW);   // u plane
        const float* f1 = f0 + HW;                       // v plane

        const float px = xf + u - 0.5f;
        const float py = yf + v - 0.5f;

        const int x0 = __float2int_rd(px);
        const int y0 = __float2int_rd(py);

        const float wx1 = px - (float)x0;
        const float wy1 = py - (float)y0;
        const float wx0 = 1.0f - wx1;
        const float wy0 = 1.0f - wy1;

        const bool vx0 = (x0 >= 0) && (x0 <= Wc - 1);
        const bool vx1 = (x0 >= -1) && (x0 <= Wc - 2);
        const bool vy0 = (y0 >= 0) && (y0 <= Hc - 1);
        const bool vy1 = (y0 >= -1) && (y0 <= Hc - 2);

        const int xc0 = min(max(x0, 0), Wc - 1);
        const int xc1 = min(max(x0 + 1, 0), Wc - 1);
        const int yc0 = min(max(y0, 0), Hc - 1);
        const int yc1 = min(max(y0 + 1, 0), Hc - 1);

        const float w00 = wx0 * wy0 * ((vx0 && vy0) ? 1.0f : 0.0f);
        const float w10 = wx1 * wy0 * ((vx1 && vy0) ? 1.0f : 0.0f);
        const float w01 = wx0 * wy1 * ((vx0 && vy1) ? 1.0f : 0.0f);
        const float w11 = wx1 * wy1 * ((vx1 && vy1) ? 1.0f : 0.0f);

        const int r0 = yc0 * Wc;
        const int r1 = yc1 * Wc;
        const int i00 = r0 + xc0;
        const int i10 = r0 + xc1;
        const int i01 = r1 + xc0;
        const int i11 = r1 + xc1;

        // 8 independent scalar gathers -> MLP 8; cheapest divergent mode.
        const float a00 = __ldg(f0 + i00);
        const float a10 = __ldg(f0 + i10);
        const float a01 = __ldg(f0 + i01);
        const float a11 = __ldg(f0 + i11);
        const float b00 = __ldg(f1 + i00);
        const float b10 = __ldg(f1 + i10);
        const float b01 = __ldg(f1 + i01);
        const float b11 = __ldg(f1 + i11);

        // Same summation order as reference: ((c00 + c10) + c01) + c11
        const float s0 = ((w00 * a00 + w10 * a10) + w01 * a01) + w11 * a11;
        const float s1 = ((w00 * b00 + w10 * b10) + w01 * b01) + w11 * b11;

        u += s0;
        v += s1;
    }

    const int p = y * Wc + x;
    float* ob = out + (unsigned)b * (2 * HW);
    ob[p]      = u;
    ob[HW + p] = v;
}

extern "C" void kernel_launch(void* const* d_in, const int* in_sizes, int n_in,
                              void* d_out, int out_size) {
    const float* flows = (const float*)d_in[0];
    float* out = (float*)d_out;

    dim3 grid(Wc / 64, Hc / 4, Bc);   // exact cover, no tails
    dim3 block(256);
    flow_composite_kernel<<<grid, block>>>(flows, out);
}